// round 1
// baseline (speedup 1.0000x reference)
#include <cuda_runtime.h>
#include <cuda_bf16.h>
#include <math.h>
#include <math_constants.h>

// Problem constants
#define BSZ   2
#define TSEQ  2048
#define DIM   2048
#define NH    16
#define NHKV  4
#define HD    128
#define KVDIM (NHKV*HD)     // 512
#define GROUP (NH/NHKV)     // 4
#define RANK  16
#define BT    (BSZ*TSEQ)    // 4096

// ---------------- scratch (device globals; no allocation allowed) ----------
__device__ float g_Wq[DIM*DIM];
__device__ float g_Wk[DIM*KVDIM];
__device__ float g_Wv[DIM*KVDIM];
__device__ float g_Wp[DIM*DIM];
__device__ float g_q[BT*DIM];
__device__ float g_k[BT*KVDIM];
__device__ float g_v[BT*KVDIM];
__device__ float g_y[BT*DIM];

// ---------------- effective weights: W + A@B (rank 16) ---------------------
__global__ void effw_kernel(const float* __restrict__ W,
                            const float* __restrict__ A,
                            const float* __restrict__ Bm,
                            float* __restrict__ Wo, int N)
{
    int idx = blockIdx.x * blockDim.x + threadIdx.x;
    int total = DIM * N;
    if (idx >= total) return;
    int i = idx / N, j = idx % N;
    float s = W[idx];
    #pragma unroll
    for (int r = 0; r < RANK; r++)
        s += A[i*RANK + r] * Bm[r*N + j];
    Wo[idx] = s;
}

// ---------------- fp32 SGEMM: C[M,N] = A[M,K] @ B[K,N] ---------------------
// BM=BN=128, BK=8, 8x8 per thread, 256 threads. All dims divide evenly here.
#define GBM 128
#define GBN 128
#define GBK 8
#define GTM 8
#define GTN 8

__global__ __launch_bounds__(256)
void sgemm_kernel(int M, int N, int K,
                  const float* __restrict__ A,
                  const float* __restrict__ B,
                  float* __restrict__ C)
{
    __shared__ float As[GBK][GBM];
    __shared__ float Bs[GBK][GBN];

    int tid  = threadIdx.x;
    int brow = blockIdx.y, bcol = blockIdx.x;

    A += (size_t)brow * GBM * K;
    B += (size_t)bcol * GBN;
    C += (size_t)brow * GBM * N + (size_t)bcol * GBN;

    int aRow = tid >> 1;            // 0..127
    int aCol = (tid & 1) * 4;       // 0 or 4
    int bRow = tid >> 5;            // 0..7
    int bCol = (tid & 31) * 4;      // 0..124

    int tRow = (tid >> 4) * GTM;    // 0..120
    int tCol = (tid & 15) * GTN;    // 0..120

    float acc[GTM][GTN] = {};
    float regM[GTM], regN[GTN];

    for (int k0 = 0; k0 < K; k0 += GBK) {
        float4 a4 = *(const float4*)(A + (size_t)aRow * K + k0 + aCol);
        As[aCol+0][aRow] = a4.x;
        As[aCol+1][aRow] = a4.y;
        As[aCol+2][aRow] = a4.z;
        As[aCol+3][aRow] = a4.w;
        float4 b4 = *(const float4*)(B + (size_t)(k0 + bRow) * N + bCol);
        *(float4*)(&Bs[bRow][bCol]) = b4;
        __syncthreads();

        #pragma unroll
        for (int k = 0; k < GBK; k++) {
            float4 m0 = *(const float4*)(&As[k][tRow]);
            float4 m1 = *(const float4*)(&As[k][tRow+4]);
            regM[0]=m0.x; regM[1]=m0.y; regM[2]=m0.z; regM[3]=m0.w;
            regM[4]=m1.x; regM[5]=m1.y; regM[6]=m1.z; regM[7]=m1.w;
            float4 n0 = *(const float4*)(&Bs[k][tCol]);
            float4 n1 = *(const float4*)(&Bs[k][tCol+4]);
            regN[0]=n0.x; regN[1]=n0.y; regN[2]=n0.z; regN[3]=n0.w;
            regN[4]=n1.x; regN[5]=n1.y; regN[6]=n1.z; regN[7]=n1.w;
            #pragma unroll
            for (int m = 0; m < GTM; m++)
                #pragma unroll
                for (int n = 0; n < GTN; n++)
                    acc[m][n] = fmaf(regM[m], regN[n], acc[m][n]);
        }
        __syncthreads();
    }

    #pragma unroll
    for (int m = 0; m < GTM; m++) {
        #pragma unroll
        for (int n = 0; n < GTN; n += 4) {
            float4 v = make_float4(acc[m][n], acc[m][n+1], acc[m][n+2], acc[m][n+3]);
            *(float4*)(C + (size_t)(tRow + m) * N + tCol + n) = v;
        }
    }
}

// ---------------- RMSnorm + RoPE (+gain) : one warp per (b,t,head) ---------
__global__ void normrope_kernel(float* __restrict__ X, int nheads, int rowdim,
                                const float* __restrict__ gain)
{
    int gthr = blockIdx.x * blockDim.x + threadIdx.x;
    int w    = gthr >> 5;
    int lane = gthr & 31;
    int total = BT * nheads;
    if (w >= total) return;
    int bt = w / nheads, hh = w % nheads;
    int t = bt % TSEQ;

    float* row = X + (size_t)bt * rowdim + hh * HD;
    float v0 = row[lane], v1 = row[lane+32], v2 = row[lane+64], v3 = row[lane+96];

    float ss = v0*v0 + v1*v1 + v2*v2 + v3*v3;
    #pragma unroll
    for (int o = 16; o; o >>= 1) ss += __shfl_xor_sync(0xffffffffu, ss, o);

    float f = rsqrtf(ss * (1.0f/128.0f) + 1.1920929e-7f);
    if (gain) f *= gain[hh];

    // rope over first 64 dims, pairs (d, d+32), freq index = lane
    float invfreq = powf(10000.0f, -(float)lane * (1.0f/32.0f));
    float ang = (float)t * invfreq;
    float s, c;
    sincosf(ang, &s, &c);

    row[lane]    = ( v0*c + v1*s) * f;
    row[lane+32] = (-v0*s + v1*c) * f;
    row[lane+64] = v2 * f;
    row[lane+96] = v3 * f;
}

// ---------------- causal flash attention -----------------------------------
#define ABQ 64
#define ABK 64
#define HDP 132   // padded stride for 128-dim rows
#define SSP 65    // padded stride for 64-wide score rows

__global__ __launch_bounds__(256)
void attn_kernel(const float* __restrict__ Q,
                 const float* __restrict__ Kg,
                 const float* __restrict__ Vg,
                 float* __restrict__ Y)
{
    extern __shared__ float sm[];
    float* Qs   = sm;                      // ABQ * HDP
    float* Ks   = Qs + ABQ*HDP;            // ABK * HDP
    float* Vs   = Ks + ABK*HDP;            // ABK * HDP
    float* Ss   = Vs + ABK*HDP;            // ABQ * SSP
    float* rowM = Ss + ABQ*SSP;            // ABQ
    float* rowL = rowM + ABQ;              // ABQ
    float* rowC = rowL + ABQ;              // ABQ

    int qt = blockIdx.x, h = blockIdx.y, b = blockIdx.z;
    int kh = h / GROUP;
    int q0 = qt * ABQ;
    int tid = threadIdx.x;
    int ty = tid >> 4, tx = tid & 15;      // 16 x 16 thread grid

    const float scale = 0.08838834764831845f;  // 128^-0.5

    // stage Q tile
    for (int e = tid; e < ABQ * (HD/4); e += 256) {
        int r = e >> 5, c4 = e & 31;
        float4 v = *(const float4*)(Q + ((size_t)(b*TSEQ + q0 + r)) * DIM + h*HD + c4*4);
        *(float4*)(Qs + r*HDP + c4*4) = v;
    }
    if (tid < ABQ) { rowM[tid] = -CUDART_INF_F; rowL[tid] = 0.0f; }

    float acc[4][8] = {};

    for (int kt = 0; kt <= qt; kt++) {
        int s0 = kt * ABK;
        __syncthreads();   // protect Ks/Vs/Ss reuse
        for (int e = tid; e < ABK * (HD/4); e += 256) {
            int r = e >> 5, c4 = e & 31;
            size_t gofs = ((size_t)(b*TSEQ + s0 + r)) * KVDIM + kh*HD + c4*4;
            *(float4*)(Ks + r*HDP + c4*4) = *(const float4*)(Kg + gofs);
            *(float4*)(Vs + r*HDP + c4*4) = *(const float4*)(Vg + gofs);
        }
        __syncthreads();

        // S = Q K^T  (each thread 4x4)
        float sacc[4][4] = {};
        #pragma unroll 4
        for (int kk = 0; kk < HD; kk++) {
            float rq[4], rk[4];
            #pragma unroll
            for (int m = 0; m < 4; m++) rq[m] = Qs[(ty*4+m)*HDP + kk];
            #pragma unroll
            for (int n = 0; n < 4; n++) rk[n] = Ks[(tx*4+n)*HDP + kk];
            #pragma unroll
            for (int m = 0; m < 4; m++)
                #pragma unroll
                for (int n = 0; n < 4; n++)
                    sacc[m][n] = fmaf(rq[m], rk[n], sacc[m][n]);
        }
        bool diag = (kt == qt);
        #pragma unroll
        for (int m = 0; m < 4; m++) {
            int r = ty*4 + m;
            #pragma unroll
            for (int n = 0; n < 4; n++) {
                int c = tx*4 + n;
                float s = sacc[m][n] * scale;
                if (diag && c > r) s = -CUDART_INF_F;
                Ss[r*SSP + c] = s;
            }
        }
        __syncthreads();

        // online softmax, one thread per row
        if (tid < ABQ) {
            int r = tid;
            float mold = rowM[r];
            float mx = mold;
            for (int j = 0; j < ABK; j++) mx = fmaxf(mx, Ss[r*SSP + j]);
            float corr = expf(mold - mx);
            float sum = 0.0f;
            for (int j = 0; j < ABK; j++) {
                float p = expf(Ss[r*SSP + j] - mx);
                Ss[r*SSP + j] = p;
                sum += p;
            }
            rowM[r] = mx;
            rowL[r] = rowL[r] * corr + sum;
            rowC[r] = corr;
        }
        __syncthreads();

        // O = O*corr + P @ V (each thread 4 rows x 8 cols)
        float cr[4];
        #pragma unroll
        for (int m = 0; m < 4; m++) cr[m] = rowC[ty*4+m];
        #pragma unroll
        for (int m = 0; m < 4; m++)
            #pragma unroll
            for (int n = 0; n < 8; n++) acc[m][n] *= cr[m];

        for (int j = 0; j < ABK; j++) {
            float rp[4];
            #pragma unroll
            for (int m = 0; m < 4; m++) rp[m] = Ss[(ty*4+m)*SSP + j];
            float4 v0 = *(const float4*)(Vs + j*HDP + tx*8);
            float4 v1 = *(const float4*)(Vs + j*HDP + tx*8 + 4);
            float rv[8] = {v0.x,v0.y,v0.z,v0.w,v1.x,v1.y,v1.z,v1.w};
            #pragma unroll
            for (int m = 0; m < 4; m++)
                #pragma unroll
                for (int n = 0; n < 8; n++)
                    acc[m][n] = fmaf(rp[m], rv[n], acc[m][n]);
        }
    }

    // write out (divide by l)
    #pragma unroll
    for (int m = 0; m < 4; m++) {
        int r = ty*4 + m;
        float invl = 1.0f / rowL[r];
        float* dst = Y + ((size_t)(b*TSEQ + q0 + r)) * DIM + h*HD + tx*8;
        float4 o0 = make_float4(acc[m][0]*invl, acc[m][1]*invl, acc[m][2]*invl, acc[m][3]*invl);
        float4 o1 = make_float4(acc[m][4]*invl, acc[m][5]*invl, acc[m][6]*invl, acc[m][7]*invl);
        *(float4*)(dst)     = o0;
        *(float4*)(dst + 4) = o1;
    }
}

// ---------------- v-direction projection removal ---------------------------
__global__ void vproj_kernel(const float* __restrict__ V, float* __restrict__ Y)
{
    int gthr = blockIdx.x * blockDim.x + threadIdx.x;
    int w    = gthr >> 5;
    int lane = gthr & 31;
    if (w >= BT * NHKV) return;
    int bt = w / NHKV, kh = w % NHKV;

    const float* vrow = V + (size_t)bt * KVDIM + kh * HD;
    float v0 = vrow[lane], v1 = vrow[lane+32], v2 = vrow[lane+64], v3 = vrow[lane+96];
    float ss = v0*v0 + v1*v1 + v2*v2 + v3*v3;
    #pragma unroll
    for (int o = 16; o; o >>= 1) ss += __shfl_xor_sync(0xffffffffu, ss, o);
    float norm = sqrtf(ss);
    float inv = 1.0f / fmaxf(norm, 1e-12f);
    float n0 = v0*inv, n1 = v1*inv, n2 = v2*inv, n3 = v3*inv;

    #pragma unroll
    for (int g = 0; g < GROUP; g++) {
        int hh = kh * GROUP + g;
        float* yrow = Y + (size_t)bt * DIM + hh * HD;
        float y0 = yrow[lane], y1 = yrow[lane+32], y2 = yrow[lane+64], y3 = yrow[lane+96];
        float d = y0*n0 + y1*n1 + y2*n2 + y3*n3;
        #pragma unroll
        for (int o = 16; o; o >>= 1) d += __shfl_xor_sync(0xffffffffu, d, o);
        yrow[lane]    = y0 - d*n0;
        yrow[lane+32] = y1 - d*n1;
        yrow[lane+64] = y2 - d*n2;
        yrow[lane+96] = y3 - d*n3;
    }
}

// ---------------- launcher --------------------------------------------------
extern "C" void kernel_launch(void* const* d_in, const int* in_sizes, int n_in,
                              void* d_out, int out_size)
{
    const float* x     = (const float*)d_in[0];
    const float* Wq    = (const float*)d_in[1];
    const float* Wk    = (const float*)d_in[2];
    const float* Wv    = (const float*)d_in[3];
    const float* Wp    = (const float*)d_in[4];
    const float* qgain = (const float*)d_in[5];
    const float* qA    = (const float*)d_in[6];
    const float* qB    = (const float*)d_in[7];
    const float* kA    = (const float*)d_in[8];
    const float* kB    = (const float*)d_in[9];
    const float* vA    = (const float*)d_in[10];
    const float* vB    = (const float*)d_in[11];
    const float* pA    = (const float*)d_in[12];
    const float* pB    = (const float*)d_in[13];
    float* out = (float*)d_out;

    float *wq, *wk, *wv, *wp, *q, *k, *v, *y;
    cudaGetSymbolAddress((void**)&wq, g_Wq);
    cudaGetSymbolAddress((void**)&wk, g_Wk);
    cudaGetSymbolAddress((void**)&wv, g_Wv);
    cudaGetSymbolAddress((void**)&wp, g_Wp);
    cudaGetSymbolAddress((void**)&q,  g_q);
    cudaGetSymbolAddress((void**)&k,  g_k);
    cudaGetSymbolAddress((void**)&v,  g_v);
    cudaGetSymbolAddress((void**)&y,  g_y);

    // 1) effective weights (fold rank-16 LoRA into dense weights)
    effw_kernel<<<(DIM*DIM   + 255)/256, 256>>>(Wq, qA, qB, wq, DIM);
    effw_kernel<<<(DIM*KVDIM + 255)/256, 256>>>(Wk, kA, kB, wk, KVDIM);
    effw_kernel<<<(DIM*KVDIM + 255)/256, 256>>>(Wv, vA, vB, wv, KVDIM);
    effw_kernel<<<(DIM*DIM   + 255)/256, 256>>>(Wp, pA, pB, wp, DIM);

    // 2) q/k/v projections
    dim3 gq(DIM/GBN,   BT/GBM);
    dim3 gk(KVDIM/GBN, BT/GBM);
    sgemm_kernel<<<gq, 256>>>(BT, DIM,   DIM, x, wq, q);
    sgemm_kernel<<<gk, 256>>>(BT, KVDIM, DIM, x, wk, k);
    sgemm_kernel<<<gk, 256>>>(BT, KVDIM, DIM, x, wv, v);

    // 3) per-head RMSnorm + RoPE (+gain on q)
    {
        int wq_n = BT * NH;    // warps
        int wk_n = BT * NHKV;
        normrope_kernel<<<(wq_n*32 + 255)/256, 256>>>(q, NH,   DIM,   qgain);
        normrope_kernel<<<(wk_n*32 + 255)/256, 256>>>(k, NHKV, KVDIM, nullptr);
    }

    // 4) causal attention (flash style)
    {
        const int ATT_SMEM = (3*ABQ*HDP + ABQ*SSP + 3*ABQ) * (int)sizeof(float); // 118784
        cudaFuncSetAttribute(attn_kernel, cudaFuncAttributeMaxDynamicSharedMemorySize, ATT_SMEM);
        dim3 ga(TSEQ/ABQ, NH, BSZ);
        attn_kernel<<<ga, 256, ATT_SMEM>>>(q, k, v, y);
    }

    // 5) remove projection onto normalized v
    {
        int wv_n = BT * NHKV;
        vproj_kernel<<<(wv_n*32 + 255)/256, 256>>>(v, y);
    }

    // 6) output projection
    sgemm_kernel<<<gq, 256>>>(BT, DIM, DIM, y, wp, out);
}

// round 3
// speedup vs baseline: 1.3100x; 1.3100x over previous
#include <cuda_runtime.h>
#include <cuda_bf16.h>
#include <math.h>
#include <math_constants.h>
#include <stdint.h>

// Problem constants
#define BSZ   2
#define TSEQ  2048
#define DIM   2048
#define NH    16
#define NHKV  4
#define HD    128
#define KVDIM (NHKV*HD)     // 512
#define GROUP (NH/NHKV)     // 4
#define RANK  16
#define BT    (BSZ*TSEQ)    // 4096

// ---------------- scratch (device globals; no allocation allowed) ----------
// bf16 hi/lo split operands (weights stored TRANSPOSED [N][K])
__device__ __nv_bfloat16 g_WqTh[DIM*DIM],   g_WqTl[DIM*DIM];
__device__ __nv_bfloat16 g_WkTh[KVDIM*DIM], g_WkTl[KVDIM*DIM];
__device__ __nv_bfloat16 g_WvTh[KVDIM*DIM], g_WvTl[KVDIM*DIM];
__device__ __nv_bfloat16 g_WpTh[DIM*DIM],   g_WpTl[DIM*DIM];
__device__ __nv_bfloat16 g_xh[BT*DIM],  g_xl[BT*DIM];
__device__ __nv_bfloat16 g_yh[BT*DIM],  g_yl[BT*DIM];
// fp32 activations
__device__ float g_q[BT*DIM];
__device__ float g_k[BT*KVDIM];
__device__ float g_v[BT*KVDIM];
__device__ float g_y[BT*DIM];

__device__ __forceinline__ void split2bf(float v, __nv_bfloat16& h, __nv_bfloat16& l) {
    h = __float2bfloat16_rn(v);
    l = __float2bfloat16_rn(v - __bfloat162float(h));
}

// ---- effective weights W + A@B, transposed to [N][K], split to bf16 hi/lo -
__global__ void effw_splitT_kernel(const float* __restrict__ W,
                                   const float* __restrict__ A,
                                   const float* __restrict__ Bm,
                                   __nv_bfloat16* __restrict__ H,
                                   __nv_bfloat16* __restrict__ L, int N)
{
    int idx = blockIdx.x * blockDim.x + threadIdx.x;
    if (idx >= N * DIM) return;
    int n = idx / DIM, k = idx % DIM;
    float s = W[(size_t)k * N + n];
    #pragma unroll
    for (int r = 0; r < RANK; r++)
        s += A[k*RANK + r] * Bm[r*N + n];
    split2bf(s, H[idx], L[idx]);
}

// ---- split fp32 activation into bf16 hi/lo ---------------------------------
__global__ void split_kernel(const float* __restrict__ X, int count,
                             __nv_bfloat16* __restrict__ H,
                             __nv_bfloat16* __restrict__ L)
{
    int idx = blockIdx.x * blockDim.x + threadIdx.x;
    if (idx >= count) return;
    split2bf(X[idx], H[idx], L[idx]);
}

// ---------------- bf16x3 tensor-core GEMM ----------------------------------
// C[M,N](fp32) = (Ah+Al)[M,K] @ (Bh+Bl)^T  with B stored [N][K].
// 128x128x32 tile, 4 warps (2x2), warp tile 64x64, m16n8k16 mma.
// hi*hi + hi*lo + lo*hi. cp.async double buffered. Row stride 40 bf16.
#define TBM 128
#define TBN 128
#define TBK 32
#define STR 40      // bf16 elements per smem row (conflict-free: 20 words)

__device__ __forceinline__ void cpa16(uint32_t dst, const void* src) {
    asm volatile("cp.async.ca.shared.global [%0], [%1], 16;\n" :: "r"(dst), "l"(src));
}
__device__ __forceinline__ void cpa_commit() {
    asm volatile("cp.async.commit_group;\n");
}
__device__ __forceinline__ void cpa_wait0() {
    asm volatile("cp.async.wait_group 0;\n");
}
__device__ __forceinline__ void mma_bf16(float& d0, float& d1, float& d2, float& d3,
                                         uint32_t a0, uint32_t a1, uint32_t a2, uint32_t a3,
                                         uint32_t b0, uint32_t b1) {
    asm volatile(
        "mma.sync.aligned.m16n8k16.row.col.f32.bf16.bf16.f32 "
        "{%0,%1,%2,%3}, {%4,%5,%6,%7}, {%8,%9}, {%0,%1,%2,%3};\n"
        : "+f"(d0), "+f"(d1), "+f"(d2), "+f"(d3)
        : "r"(a0), "r"(a1), "r"(a2), "r"(a3), "r"(b0), "r"(b1));
}

__global__ __launch_bounds__(128)
void bf16x3gemm_kernel(int M, int N, int K,
                       const __nv_bfloat16* __restrict__ Ah,
                       const __nv_bfloat16* __restrict__ Al,
                       const __nv_bfloat16* __restrict__ Bh,   // [N][K]
                       const __nv_bfloat16* __restrict__ Bl,
                       float* __restrict__ C)
{
    extern __shared__ __nv_bfloat16 smem[];
    __nv_bfloat16* sAh = smem;                     // 2 * 128*STR
    __nv_bfloat16* sAl = sAh + 2*TBM*STR;
    __nv_bfloat16* sBh = sAl + 2*TBM*STR;
    __nv_bfloat16* sBl = sBh + 2*TBN*STR;

    int tid  = threadIdx.x;
    int warp = tid >> 5, lane = tid & 31;
    int warpM = warp >> 1, warpN = warp & 1;
    int gid = lane >> 2, tig = lane & 3;

    const __nv_bfloat16* Ahb = Ah + (size_t)blockIdx.y * TBM * K;
    const __nv_bfloat16* Alb = Al + (size_t)blockIdx.y * TBM * K;
    const __nv_bfloat16* Bhb = Bh + (size_t)blockIdx.x * TBN * K;
    const __nv_bfloat16* Blb = Bl + (size_t)blockIdx.x * TBN * K;
    float* Cb = C + (size_t)blockIdx.y * TBM * N + (size_t)blockIdx.x * TBN;

    // staging coords: row = tid>>2 (+32i), col8 = tid&3 (8 bf16 per cp)
    int srow = tid >> 2;
    int scol = (tid & 3) * 8;

    uint32_t uAh = (uint32_t)__cvta_generic_to_shared(sAh);
    uint32_t uAl = (uint32_t)__cvta_generic_to_shared(sAl);
    uint32_t uBh = (uint32_t)__cvta_generic_to_shared(sBh);
    uint32_t uBl = (uint32_t)__cvta_generic_to_shared(sBl);

    float acc[4][8][4];
    #pragma unroll
    for (int m = 0; m < 4; m++)
        #pragma unroll
        for (int n = 0; n < 8; n++)
            #pragma unroll
            for (int i = 0; i < 4; i++) acc[m][n][i] = 0.0f;

    int ntiles = K / TBK;

    auto issue = [&](int buf, int kt) {
        uint32_t bofs = (uint32_t)(buf * TBM * STR * 2);
        #pragma unroll
        for (int i = 0; i < 4; i++) {
            int r = srow + i * 32;
            uint32_t dofs = (uint32_t)((r * STR + scol) * 2);
            size_t gofs = (size_t)r * K + (size_t)kt * TBK + scol;
            cpa16(uAh + bofs + dofs, Ahb + gofs);
            cpa16(uAl + bofs + dofs, Alb + gofs);
            cpa16(uBh + bofs + dofs, Bhb + gofs);
            cpa16(uBl + bofs + dofs, Blb + gofs);
        }
        cpa_commit();
    };

    issue(0, 0);
    int buf = 0;

    for (int kt = 0; kt < ntiles; kt++) {
        cpa_wait0();
        __syncthreads();
        if (kt + 1 < ntiles) issue(buf ^ 1, kt + 1);

        const __nv_bfloat16* Ahs = sAh + buf * TBM * STR;
        const __nv_bfloat16* Als = sAl + buf * TBM * STR;
        const __nv_bfloat16* Bhs = sBh + buf * TBN * STR;
        const __nv_bfloat16* Bls = sBl + buf * TBN * STR;

        #pragma unroll
        for (int ks = 0; ks < TBK; ks += 16) {
            uint32_t afh[4][4], afl[4][4];
            #pragma unroll
            for (int mt = 0; mt < 4; mt++) {
                int r0 = warpM*64 + mt*16;
                const __nv_bfloat16* ah = Ahs + (size_t)r0 * STR + ks;
                const __nv_bfloat16* al = Als + (size_t)r0 * STR + ks;
                afh[mt][0] = *(const uint32_t*)(ah + (size_t) gid      * STR + 2*tig);
                afh[mt][1] = *(const uint32_t*)(ah + (size_t)(gid + 8) * STR + 2*tig);
                afh[mt][2] = *(const uint32_t*)(ah + (size_t) gid      * STR + 2*tig + 8);
                afh[mt][3] = *(const uint32_t*)(ah + (size_t)(gid + 8) * STR + 2*tig + 8);
                afl[mt][0] = *(const uint32_t*)(al + (size_t) gid      * STR + 2*tig);
                afl[mt][1] = *(const uint32_t*)(al + (size_t)(gid + 8) * STR + 2*tig);
                afl[mt][2] = *(const uint32_t*)(al + (size_t) gid      * STR + 2*tig + 8);
                afl[mt][3] = *(const uint32_t*)(al + (size_t)(gid + 8) * STR + 2*tig + 8);
            }
            uint32_t bfh[8][2], bfl[8][2];
            #pragma unroll
            for (int nt = 0; nt < 8; nt++) {
                int n0 = warpN*64 + nt*8 + gid;
                const __nv_bfloat16* bh = Bhs + (size_t)n0 * STR + ks;
                const __nv_bfloat16* bl = Bls + (size_t)n0 * STR + ks;
                bfh[nt][0] = *(const uint32_t*)(bh + 2*tig);
                bfh[nt][1] = *(const uint32_t*)(bh + 2*tig + 8);
                bfl[nt][0] = *(const uint32_t*)(bl + 2*tig);
                bfl[nt][1] = *(const uint32_t*)(bl + 2*tig + 8);
            }
            #pragma unroll
            for (int mt = 0; mt < 4; mt++)
                #pragma unroll
                for (int nt = 0; nt < 8; nt++) {
                    mma_bf16(acc[mt][nt][0], acc[mt][nt][1], acc[mt][nt][2], acc[mt][nt][3],
                             afh[mt][0], afh[mt][1], afh[mt][2], afh[mt][3],
                             bfh[nt][0], bfh[nt][1]);
                    mma_bf16(acc[mt][nt][0], acc[mt][nt][1], acc[mt][nt][2], acc[mt][nt][3],
                             afh[mt][0], afh[mt][1], afh[mt][2], afh[mt][3],
                             bfl[nt][0], bfl[nt][1]);
                    mma_bf16(acc[mt][nt][0], acc[mt][nt][1], acc[mt][nt][2], acc[mt][nt][3],
                             afl[mt][0], afl[mt][1], afl[mt][2], afl[mt][3],
                             bfh[nt][0], bfh[nt][1]);
                }
        }
        __syncthreads();
        buf ^= 1;
    }

    #pragma unroll
    for (int mt = 0; mt < 4; mt++) {
        int r0 = warpM*64 + mt*16 + gid;
        #pragma unroll
        for (int nt = 0; nt < 8; nt++) {
            int c0 = warpN*64 + nt*8 + tig*2;
            *(float2*)(Cb + (size_t) r0      * N + c0) = make_float2(acc[mt][nt][0], acc[mt][nt][1]);
            *(float2*)(Cb + (size_t)(r0 + 8) * N + c0) = make_float2(acc[mt][nt][2], acc[mt][nt][3]);
        }
    }
}

// ---------------- RMSnorm + RoPE (+gain) : one warp per (b,t,head) ---------
__global__ void normrope_kernel(float* __restrict__ X, int nheads, int rowdim,
                                const float* __restrict__ gain)
{
    int gthr = blockIdx.x * blockDim.x + threadIdx.x;
    int w    = gthr >> 5;
    int lane = gthr & 31;
    int total = BT * nheads;
    if (w >= total) return;
    int bt = w / nheads, hh = w % nheads;
    int t = bt % TSEQ;

    float* row = X + (size_t)bt * rowdim + hh * HD;
    float v0 = row[lane], v1 = row[lane+32], v2 = row[lane+64], v3 = row[lane+96];

    float ss = v0*v0 + v1*v1 + v2*v2 + v3*v3;
    #pragma unroll
    for (int o = 16; o; o >>= 1) ss += __shfl_xor_sync(0xffffffffu, ss, o);

    float f = rsqrtf(ss * (1.0f/128.0f) + 1.1920929e-7f);
    if (gain) f *= gain[hh];

    float invfreq = powf(10000.0f, -(float)lane * (1.0f/32.0f));
    float ang = (float)t * invfreq;
    float s, c;
    sincosf(ang, &s, &c);

    row[lane]    = ( v0*c + v1*s) * f;
    row[lane+32] = (-v0*s + v1*c) * f;
    row[lane+64] = v2 * f;
    row[lane+96] = v3 * f;
}

// ---------------- causal flash attention (fp32 SIMT, known-good) -----------
#define ABQ 64
#define ABK 64
#define HDP 132
#define SSP 65

__global__ __launch_bounds__(256)
void attn_kernel(const float* __restrict__ Q,
                 const float* __restrict__ Kg,
                 const float* __restrict__ Vg,
                 float* __restrict__ Y)
{
    extern __shared__ float sm[];
    float* Qs   = sm;
    float* Ks   = Qs + ABQ*HDP;
    float* Vs   = Ks + ABK*HDP;
    float* Ss   = Vs + ABK*HDP;
    float* rowM = Ss + ABQ*SSP;
    float* rowL = rowM + ABQ;
    float* rowC = rowL + ABQ;

    int qt = blockIdx.x, h = blockIdx.y, b = blockIdx.z;
    int kh = h / GROUP;
    int q0 = qt * ABQ;
    int tid = threadIdx.x;
    int ty = tid >> 4, tx = tid & 15;

    const float scale = 0.08838834764831845f;

    for (int e = tid; e < ABQ * (HD/4); e += 256) {
        int r = e >> 5, c4 = e & 31;
        float4 v = *(const float4*)(Q + ((size_t)(b*TSEQ + q0 + r)) * DIM + h*HD + c4*4);
        *(float4*)(Qs + r*HDP + c4*4) = v;
    }
    if (tid < ABQ) { rowM[tid] = -CUDART_INF_F; rowL[tid] = 0.0f; }

    float acc[4][8] = {};

    for (int kt = 0; kt <= qt; kt++) {
        int s0 = kt * ABK;
        __syncthreads();
        for (int e = tid; e < ABK * (HD/4); e += 256) {
            int r = e >> 5, c4 = e & 31;
            size_t gofs = ((size_t)(b*TSEQ + s0 + r)) * KVDIM + kh*HD + c4*4;
            *(float4*)(Ks + r*HDP + c4*4) = *(const float4*)(Kg + gofs);
            *(float4*)(Vs + r*HDP + c4*4) = *(const float4*)(Vg + gofs);
        }
        __syncthreads();

        float sacc[4][4] = {};
        #pragma unroll 4
        for (int kk = 0; kk < HD; kk++) {
            float rq[4], rk[4];
            #pragma unroll
            for (int m = 0; m < 4; m++) rq[m] = Qs[(ty*4+m)*HDP + kk];
            #pragma unroll
            for (int n = 0; n < 4; n++) rk[n] = Ks[(tx*4+n)*HDP + kk];
            #pragma unroll
            for (int m = 0; m < 4; m++)
                #pragma unroll
                for (int n = 0; n < 4; n++)
                    sacc[m][n] = fmaf(rq[m], rk[n], sacc[m][n]);
        }
        bool diag = (kt == qt);
        #pragma unroll
        for (int m = 0; m < 4; m++) {
            int r = ty*4 + m;
            #pragma unroll
            for (int n = 0; n < 4; n++) {
                int c = tx*4 + n;
                float s = sacc[m][n] * scale;
                if (diag && c > r) s = -CUDART_INF_F;
                Ss[r*SSP + c] = s;
            }
        }
        __syncthreads();

        if (tid < ABQ) {
            int r = tid;
            float mold = rowM[r];
            float mx = mold;
            for (int j = 0; j < ABK; j++) mx = fmaxf(mx, Ss[r*SSP + j]);
            float corr = expf(mold - mx);
            float sum = 0.0f;
            for (int j = 0; j < ABK; j++) {
                float p = expf(Ss[r*SSP + j] - mx);
                Ss[r*SSP + j] = p;
                sum += p;
            }
            rowM[r] = mx;
            rowL[r] = rowL[r] * corr + sum;
            rowC[r] = corr;
        }
        __syncthreads();

        float cr[4];
        #pragma unroll
        for (int m = 0; m < 4; m++) cr[m] = rowC[ty*4+m];
        #pragma unroll
        for (int m = 0; m < 4; m++)
            #pragma unroll
            for (int n = 0; n < 8; n++) acc[m][n] *= cr[m];

        for (int j = 0; j < ABK; j++) {
            float rp[4];
            #pragma unroll
            for (int m = 0; m < 4; m++) rp[m] = Ss[(ty*4+m)*SSP + j];
            float4 v0 = *(const float4*)(Vs + j*HDP + tx*8);
            float4 v1 = *(const float4*)(Vs + j*HDP + tx*8 + 4);
            float rv[8] = {v0.x,v0.y,v0.z,v0.w,v1.x,v1.y,v1.z,v1.w};
            #pragma unroll
            for (int m = 0; m < 4; m++)
                #pragma unroll
                for (int n = 0; n < 8; n++)
                    acc[m][n] = fmaf(rp[m], rv[n], acc[m][n]);
        }
    }

    #pragma unroll
    for (int m = 0; m < 4; m++) {
        int r = ty*4 + m;
        float invl = 1.0f / rowL[r];
        float* dst = Y + ((size_t)(b*TSEQ + q0 + r)) * DIM + h*HD + tx*8;
        float4 o0 = make_float4(acc[m][0]*invl, acc[m][1]*invl, acc[m][2]*invl, acc[m][3]*invl);
        float4 o1 = make_float4(acc[m][4]*invl, acc[m][5]*invl, acc[m][6]*invl, acc[m][7]*invl);
        *(float4*)(dst)     = o0;
        *(float4*)(dst + 4) = o1;
    }
}

// ---------------- v-direction projection removal ---------------------------
__global__ void vproj_kernel(const float* __restrict__ V, float* __restrict__ Y)
{
    int gthr = blockIdx.x * blockDim.x + threadIdx.x;
    int w    = gthr >> 5;
    int lane = gthr & 31;
    if (w >= BT * NHKV) return;
    int bt = w / NHKV, kh = w % NHKV;

    const float* vrow = V + (size_t)bt * KVDIM + kh * HD;
    float v0 = vrow[lane], v1 = vrow[lane+32], v2 = vrow[lane+64], v3 = vrow[lane+96];
    float ss = v0*v0 + v1*v1 + v2*v2 + v3*v3;
    #pragma unroll
    for (int o = 16; o; o >>= 1) ss += __shfl_xor_sync(0xffffffffu, ss, o);
    float norm = sqrtf(ss);
    float inv = 1.0f / fmaxf(norm, 1e-12f);
    float n0 = v0*inv, n1 = v1*inv, n2 = v2*inv, n3 = v3*inv;

    #pragma unroll
    for (int g = 0; g < GROUP; g++) {
        int hh = kh * GROUP + g;
        float* yrow = Y + (size_t)bt * DIM + hh * HD;
        float y0 = yrow[lane], y1 = yrow[lane+32], y2 = yrow[lane+64], y3 = yrow[lane+96];
        float d = y0*n0 + y1*n1 + y2*n2 + y3*n3;
        #pragma unroll
        for (int o = 16; o; o >>= 1) d += __shfl_xor_sync(0xffffffffu, d, o);
        yrow[lane]    = y0 - d*n0;
        yrow[lane+32] = y1 - d*n1;
        yrow[lane+64] = y2 - d*n2;
        yrow[lane+96] = y3 - d*n3;
    }
}

// ---------------- launcher --------------------------------------------------
extern "C" void kernel_launch(void* const* d_in, const int* in_sizes, int n_in,
                              void* d_out, int out_size)
{
    const float* x     = (const float*)d_in[0];
    const float* Wq    = (const float*)d_in[1];
    const float* Wk    = (const float*)d_in[2];
    const float* Wv    = (const float*)d_in[3];
    const float* Wp    = (const float*)d_in[4];
    const float* qgain = (const float*)d_in[5];
    const float* qA    = (const float*)d_in[6];
    const float* qB    = (const float*)d_in[7];
    const float* kA    = (const float*)d_in[8];
    const float* kB    = (const float*)d_in[9];
    const float* vA    = (const float*)d_in[10];
    const float* vB    = (const float*)d_in[11];
    const float* pA    = (const float*)d_in[12];
    const float* pB    = (const float*)d_in[13];
    float* out = (float*)d_out;

    __nv_bfloat16 *wqh,*wql,*wkh,*wkl,*wvh,*wvl,*wph,*wpl,*xh,*xl,*yh,*yl;
    float *q, *k, *v, *y;
    cudaGetSymbolAddress((void**)&wqh, g_WqTh); cudaGetSymbolAddress((void**)&wql, g_WqTl);
    cudaGetSymbolAddress((void**)&wkh, g_WkTh); cudaGetSymbolAddress((void**)&wkl, g_WkTl);
    cudaGetSymbolAddress((void**)&wvh, g_WvTh); cudaGetSymbolAddress((void**)&wvl, g_WvTl);
    cudaGetSymbolAddress((void**)&wph, g_WpTh); cudaGetSymbolAddress((void**)&wpl, g_WpTl);
    cudaGetSymbolAddress((void**)&xh,  g_xh);   cudaGetSymbolAddress((void**)&xl,  g_xl);
    cudaGetSymbolAddress((void**)&yh,  g_yh);   cudaGetSymbolAddress((void**)&yl,  g_yl);
    cudaGetSymbolAddress((void**)&q,   g_q);
    cudaGetSymbolAddress((void**)&k,   g_k);
    cudaGetSymbolAddress((void**)&v,   g_v);
    cudaGetSymbolAddress((void**)&y,   g_y);

    const int GSMEM = (2*TBM*STR + 2*TBM*STR + 2*TBN*STR + 2*TBN*STR) * (int)sizeof(__nv_bfloat16); // 81920
    cudaFuncSetAttribute(bf16x3gemm_kernel, cudaFuncAttributeMaxDynamicSharedMemorySize, GSMEM);

    // 1) fold LoRA, transpose, split to bf16 hi/lo
    effw_splitT_kernel<<<(DIM*DIM   + 255)/256, 256>>>(Wq, qA, qB, wqh, wql, DIM);
    effw_splitT_kernel<<<(KVDIM*DIM + 255)/256, 256>>>(Wk, kA, kB, wkh, wkl, KVDIM);
    effw_splitT_kernel<<<(KVDIM*DIM + 255)/256, 256>>>(Wv, vA, vB, wvh, wvl, KVDIM);
    effw_splitT_kernel<<<(DIM*DIM   + 255)/256, 256>>>(Wp, pA, pB, wph, wpl, DIM);
    split_kernel<<<(BT*DIM + 255)/256, 256>>>(x, BT*DIM, xh, xl);

    // 2) q/k/v projections (bf16x3 tensor cores)
    dim3 gq(DIM/TBN,   BT/TBM);
    dim3 gk(KVDIM/TBN, BT/TBM);
    bf16x3gemm_kernel<<<gq, 128, GSMEM>>>(BT, DIM,   DIM, xh, xl, wqh, wql, q);
    bf16x3gemm_kernel<<<gk, 128, GSMEM>>>(BT, KVDIM, DIM, xh, xl, wkh, wkl, k);
    bf16x3gemm_kernel<<<gk, 128, GSMEM>>>(BT, KVDIM, DIM, xh, xl, wvh, wvl, v);

    // 3) per-head RMSnorm + RoPE (+gain on q)
    {
        int wq_n = BT * NH;
        int wk_n = BT * NHKV;
        normrope_kernel<<<(wq_n*32 + 255)/256, 256>>>(q, NH,   DIM,   qgain);
        normrope_kernel<<<(wk_n*32 + 255)/256, 256>>>(k, NHKV, KVDIM, nullptr);
    }

    // 4) causal attention (flash style, fp32)
    {
        const int ATT_SMEM = (3*ABQ*HDP + ABQ*SSP + 3*ABQ) * (int)sizeof(float);
        cudaFuncSetAttribute(attn_kernel, cudaFuncAttributeMaxDynamicSharedMemorySize, ATT_SMEM);
        dim3 ga(TSEQ/ABQ, NH, BSZ);
        attn_kernel<<<ga, 256, ATT_SMEM>>>(q, k, v, y);
    }

    // 5) remove projection onto normalized v
    {
        int wv_n = BT * NHKV;
        vproj_kernel<<<(wv_n*32 + 255)/256, 256>>>(v, y);
    }

    // 6) output projection (bf16x3 tensor cores)
    split_kernel<<<(BT*DIM + 255)/256, 256>>>(y, BT*DIM, yh, yl);
    bf16x3gemm_kernel<<<gq, 128, GSMEM>>>(BT, DIM, DIM, yh, yl, wph, wpl, out);
}

// round 4
// speedup vs baseline: 1.9125x; 1.4600x over previous
#include <cuda_runtime.h>
#include <cuda_bf16.h>
#include <math.h>
#include <math_constants.h>
#include <stdint.h>

// Problem constants
#define BSZ   2
#define TSEQ  2048
#define DIM   2048
#define NH    16
#define NHKV  4
#define HD    128
#define KVDIM (NHKV*HD)     // 512
#define GROUP (NH/NHKV)     // 4
#define RANK  16
#define BT    (BSZ*TSEQ)    // 4096
#define QKVD  (DIM + 2*KVDIM)   // 3072 fused qkv row
#define KOFF  DIM               // 2048
#define VOFF  (DIM + KVDIM)     // 2560

// ---------------- scratch (device globals; no allocation allowed) ----------
__device__ __nv_bfloat16 g_WqkvTh[QKVD*DIM], g_WqkvTl[QKVD*DIM];  // [3072][2048]
__device__ __nv_bfloat16 g_WpTh[DIM*DIM],    g_WpTl[DIM*DIM];
__device__ __nv_bfloat16 g_xh[BT*DIM],  g_xl[BT*DIM];
__device__ __nv_bfloat16 g_yh[BT*DIM],  g_yl[BT*DIM];
__device__ float g_qkv[BT*QKVD];
__device__ float g_y[BT*DIM];

// ---- effective weights W + A@B, transposed to [N][K], split bf16 hi/lo ----
// Coalesced tiled transpose: read W[k][n] row-wise, write H/L[n][k] row-wise.
__global__ void effw_splitT_kernel(const float* __restrict__ W,
                                   const float* __restrict__ A,
                                   const float* __restrict__ Bm,
                                   __nv_bfloat16* __restrict__ H,
                                   __nv_bfloat16* __restrict__ L, int N)
{
    __shared__ float tile[32][33];
    int tn = blockIdx.x * 32;
    int tk = blockIdx.y * 32;
    int tx = threadIdx.x, ty = threadIdx.y;   // 32 x 8

    #pragma unroll
    for (int i = 0; i < 4; i++) {
        int k = tk + ty + i*8;
        int n = tn + tx;
        float s = W[(size_t)k * N + n];
        #pragma unroll
        for (int r = 0; r < RANK; r++)
            s += A[k*RANK + r] * Bm[r*N + n];
        tile[ty + i*8][tx] = s;
    }
    __syncthreads();
    #pragma unroll
    for (int i = 0; i < 4; i++) {
        int n = tn + ty + i*8;
        int k = tk + tx;
        float s = tile[tx][ty + i*8];
        __nv_bfloat16 h = __float2bfloat16_rn(s);
        H[(size_t)n * DIM + k] = h;
        L[(size_t)n * DIM + k] = __float2bfloat16_rn(s - __bfloat162float(h));
    }
}

// ---- split fp32 activation into bf16 hi/lo (vectorized) --------------------
__global__ void split_kernel(const float* __restrict__ X, int count4,
                             __nv_bfloat16* __restrict__ H,
                             __nv_bfloat16* __restrict__ L)
{
    int idx = blockIdx.x * blockDim.x + threadIdx.x;
    if (idx >= count4) return;
    float4 v = ((const float4*)X)[idx];
    __nv_bfloat16 h0 = __float2bfloat16_rn(v.x), h1 = __float2bfloat16_rn(v.y);
    __nv_bfloat16 h2 = __float2bfloat16_rn(v.z), h3 = __float2bfloat16_rn(v.w);
    __nv_bfloat162 hh0 = {h0, h1}, hh1 = {h2, h3};
    __nv_bfloat162 ll0 = {__float2bfloat16_rn(v.x - __bfloat162float(h0)),
                          __float2bfloat16_rn(v.y - __bfloat162float(h1))};
    __nv_bfloat162 ll1 = {__float2bfloat16_rn(v.z - __bfloat162float(h2)),
                          __float2bfloat16_rn(v.w - __bfloat162float(h3))};
    ((__nv_bfloat162*)H)[idx*2]   = hh0;
    ((__nv_bfloat162*)H)[idx*2+1] = hh1;
    ((__nv_bfloat162*)L)[idx*2]   = ll0;
    ((__nv_bfloat162*)L)[idx*2+1] = ll1;
}

// ---------------- bf16x3 tensor-core GEMM ----------------------------------
#define TBM 128
#define TBN 128
#define TBK 32
#define STR 40

__device__ __forceinline__ void cpa16(uint32_t dst, const void* src) {
    asm volatile("cp.async.ca.shared.global [%0], [%1], 16;\n" :: "r"(dst), "l"(src));
}
__device__ __forceinline__ void cpa_commit() {
    asm volatile("cp.async.commit_group;\n");
}
__device__ __forceinline__ void cpa_wait0() {
    asm volatile("cp.async.wait_group 0;\n");
}
__device__ __forceinline__ void mma_bf16(float& d0, float& d1, float& d2, float& d3,
                                         uint32_t a0, uint32_t a1, uint32_t a2, uint32_t a3,
                                         uint32_t b0, uint32_t b1) {
    asm volatile(
        "mma.sync.aligned.m16n8k16.row.col.f32.bf16.bf16.f32 "
        "{%0,%1,%2,%3}, {%4,%5,%6,%7}, {%8,%9}, {%0,%1,%2,%3};\n"
        : "+f"(d0), "+f"(d1), "+f"(d2), "+f"(d3)
        : "r"(a0), "r"(a1), "r"(a2), "r"(a3), "r"(b0), "r"(b1));
}

__global__ __launch_bounds__(128)
void bf16x3gemm_kernel(int M, int N, int K,
                       const __nv_bfloat16* __restrict__ Ah,
                       const __nv_bfloat16* __restrict__ Al,
                       const __nv_bfloat16* __restrict__ Bh,   // [N][K]
                       const __nv_bfloat16* __restrict__ Bl,
                       float* __restrict__ C)
{
    extern __shared__ __nv_bfloat16 smem[];
    __nv_bfloat16* sAh = smem;
    __nv_bfloat16* sAl = sAh + 2*TBM*STR;
    __nv_bfloat16* sBh = sAl + 2*TBM*STR;
    __nv_bfloat16* sBl = sBh + 2*TBN*STR;

    int tid  = threadIdx.x;
    int warp = tid >> 5, lane = tid & 31;
    int warpM = warp >> 1, warpN = warp & 1;
    int gid = lane >> 2, tig = lane & 3;

    const __nv_bfloat16* Ahb = Ah + (size_t)blockIdx.y * TBM * K;
    const __nv_bfloat16* Alb = Al + (size_t)blockIdx.y * TBM * K;
    const __nv_bfloat16* Bhb = Bh + (size_t)blockIdx.x * TBN * K;
    const __nv_bfloat16* Blb = Bl + (size_t)blockIdx.x * TBN * K;
    float* Cb = C + (size_t)blockIdx.y * TBM * N + (size_t)blockIdx.x * TBN;

    int srow = tid >> 2;
    int scol = (tid & 3) * 8;

    uint32_t uAh = (uint32_t)__cvta_generic_to_shared(sAh);
    uint32_t uAl = (uint32_t)__cvta_generic_to_shared(sAl);
    uint32_t uBh = (uint32_t)__cvta_generic_to_shared(sBh);
    uint32_t uBl = (uint32_t)__cvta_generic_to_shared(sBl);

    float acc[4][8][4];
    #pragma unroll
    for (int m = 0; m < 4; m++)
        #pragma unroll
        for (int n = 0; n < 8; n++)
            #pragma unroll
            for (int i = 0; i < 4; i++) acc[m][n][i] = 0.0f;

    int ntiles = K / TBK;

    auto issue = [&](int buf, int kt) {
        uint32_t bofs = (uint32_t)(buf * TBM * STR * 2);
        #pragma unroll
        for (int i = 0; i < 4; i++) {
            int r = srow + i * 32;
            uint32_t dofs = (uint32_t)((r * STR + scol) * 2);
            size_t gofs = (size_t)r * K + (size_t)kt * TBK + scol;
            cpa16(uAh + bofs + dofs, Ahb + gofs);
            cpa16(uAl + bofs + dofs, Alb + gofs);
            cpa16(uBh + bofs + dofs, Bhb + gofs);
            cpa16(uBl + bofs + dofs, Blb + gofs);
        }
        cpa_commit();
    };

    issue(0, 0);
    int buf = 0;

    for (int kt = 0; kt < ntiles; kt++) {
        cpa_wait0();
        __syncthreads();
        if (kt + 1 < ntiles) issue(buf ^ 1, kt + 1);

        const __nv_bfloat16* Ahs = sAh + buf * TBM * STR;
        const __nv_bfloat16* Als = sAl + buf * TBM * STR;
        const __nv_bfloat16* Bhs = sBh + buf * TBN * STR;
        const __nv_bfloat16* Bls = sBl + buf * TBN * STR;

        #pragma unroll
        for (int ks = 0; ks < TBK; ks += 16) {
            uint32_t afh[4][4], afl[4][4];
            #pragma unroll
            for (int mt = 0; mt < 4; mt++) {
                int r0 = warpM*64 + mt*16;
                const __nv_bfloat16* ah = Ahs + (size_t)r0 * STR + ks;
                const __nv_bfloat16* al = Als + (size_t)r0 * STR + ks;
                afh[mt][0] = *(const uint32_t*)(ah + (size_t) gid      * STR + 2*tig);
                afh[mt][1] = *(const uint32_t*)(ah + (size_t)(gid + 8) * STR + 2*tig);
                afh[mt][2] = *(const uint32_t*)(ah + (size_t) gid      * STR + 2*tig + 8);
                afh[mt][3] = *(const uint32_t*)(ah + (size_t)(gid + 8) * STR + 2*tig + 8);
                afl[mt][0] = *(const uint32_t*)(al + (size_t) gid      * STR + 2*tig);
                afl[mt][1] = *(const uint32_t*)(al + (size_t)(gid + 8) * STR + 2*tig);
                afl[mt][2] = *(const uint32_t*)(al + (size_t) gid      * STR + 2*tig + 8);
                afl[mt][3] = *(const uint32_t*)(al + (size_t)(gid + 8) * STR + 2*tig + 8);
            }
            uint32_t bfh[8][2], bfl[8][2];
            #pragma unroll
            for (int nt = 0; nt < 8; nt++) {
                int n0 = warpN*64 + nt*8 + gid;
                const __nv_bfloat16* bh = Bhs + (size_t)n0 * STR + ks;
                const __nv_bfloat16* bl = Bls + (size_t)n0 * STR + ks;
                bfh[nt][0] = *(const uint32_t*)(bh + 2*tig);
                bfh[nt][1] = *(const uint32_t*)(bh + 2*tig + 8);
                bfl[nt][0] = *(const uint32_t*)(bl + 2*tig);
                bfl[nt][1] = *(const uint32_t*)(bl + 2*tig + 8);
            }
            #pragma unroll
            for (int mt = 0; mt < 4; mt++)
                #pragma unroll
                for (int nt = 0; nt < 8; nt++) {
                    mma_bf16(acc[mt][nt][0], acc[mt][nt][1], acc[mt][nt][2], acc[mt][nt][3],
                             afh[mt][0], afh[mt][1], afh[mt][2], afh[mt][3],
                             bfh[nt][0], bfh[nt][1]);
                    mma_bf16(acc[mt][nt][0], acc[mt][nt][1], acc[mt][nt][2], acc[mt][nt][3],
                             afh[mt][0], afh[mt][1], afh[mt][2], afh[mt][3],
                             bfl[nt][0], bfl[nt][1]);
                    mma_bf16(acc[mt][nt][0], acc[mt][nt][1], acc[mt][nt][2], acc[mt][nt][3],
                             afl[mt][0], afl[mt][1], afl[mt][2], afl[mt][3],
                             bfh[nt][0], bfh[nt][1]);
                }
        }
        __syncthreads();
        buf ^= 1;
    }

    #pragma unroll
    for (int mt = 0; mt < 4; mt++) {
        int r0 = warpM*64 + mt*16 + gid;
        #pragma unroll
        for (int nt = 0; nt < 8; nt++) {
            int c0 = warpN*64 + nt*8 + tig*2;
            *(float2*)(Cb + (size_t) r0      * N + c0) = make_float2(acc[mt][nt][0], acc[mt][nt][1]);
            *(float2*)(Cb + (size_t)(r0 + 8) * N + c0) = make_float2(acc[mt][nt][2], acc[mt][nt][3]);
        }
    }
}

// ---------------- RMSnorm + RoPE (+gain) : one warp per (b,t,head) ---------
__global__ void normrope_kernel(float* __restrict__ X, int nheads, int rowdim,
                                const float* __restrict__ gain)
{
    int gthr = blockIdx.x * blockDim.x + threadIdx.x;
    int w    = gthr >> 5;
    int lane = gthr & 31;
    int total = BT * nheads;
    if (w >= total) return;
    int bt = w / nheads, hh = w % nheads;
    int t = bt % TSEQ;

    float* row = X + (size_t)bt * rowdim + hh * HD;
    float v0 = row[lane], v1 = row[lane+32], v2 = row[lane+64], v3 = row[lane+96];

    float ss = v0*v0 + v1*v1 + v2*v2 + v3*v3;
    #pragma unroll
    for (int o = 16; o; o >>= 1) ss += __shfl_xor_sync(0xffffffffu, ss, o);

    float f = rsqrtf(ss * (1.0f/128.0f) + 1.1920929e-7f);
    if (gain) f *= gain[hh];

    float invfreq = powf(10000.0f, -(float)lane * (1.0f/32.0f));
    float ang = (float)t * invfreq;
    float s, c;
    sincosf(ang, &s, &c);

    row[lane]    = ( v0*c + v1*s) * f;
    row[lane+32] = (-v0*s + v1*c) * f;
    row[lane+64] = v2 * f;
    row[lane+96] = v3 * f;
}

// ---------------- causal flash attention (fp32, conflict-free S-phase) -----
#define ABQ 64
#define ABK 64
#define HDP 132
#define SSP 65

__global__ __launch_bounds__(256)
void attn_kernel(const float* __restrict__ QKV,
                 float* __restrict__ Y)
{
    extern __shared__ float sm[];
    float* Qs   = sm;
    float* Ks   = Qs + ABQ*HDP;
    float* Vs   = Ks + ABK*HDP;
    float* Ss   = Vs + ABK*HDP;
    float* rowM = Ss + ABQ*SSP;
    float* rowL = rowM + ABQ;
    float* rowC = rowL + ABQ;

    int qt = blockIdx.x, h = blockIdx.y, b = blockIdx.z;
    int kh = h / GROUP;
    int q0 = qt * ABQ;
    int tid = threadIdx.x;
    int ty = tid >> 4, tx = tid & 15;

    const float scale = 0.08838834764831845f;

    for (int e = tid; e < ABQ * (HD/4); e += 256) {
        int r = e >> 5, c4 = e & 31;
        float4 v = *(const float4*)(QKV + ((size_t)(b*TSEQ + q0 + r)) * QKVD + h*HD + c4*4);
        *(float4*)(Qs + r*HDP + c4*4) = v;
    }
    if (tid < ABQ) { rowM[tid] = -CUDART_INF_F; rowL[tid] = 0.0f; }

    float acc[4][8] = {};

    for (int kt = 0; kt <= qt; kt++) {
        int s0 = kt * ABK;
        __syncthreads();
        for (int e = tid; e < ABK * (HD/4); e += 256) {
            int r = e >> 5, c4 = e & 31;
            size_t gofs = ((size_t)(b*TSEQ + s0 + r)) * QKVD + kh*HD + c4*4;
            *(float4*)(Ks + r*HDP + c4*4) = *(const float4*)(QKV + KOFF + gofs);
            *(float4*)(Vs + r*HDP + c4*4) = *(const float4*)(QKV + VOFF + gofs);
        }
        __syncthreads();

        // S = Q K^T : float4 chunks with per-lane rotation (conflict-free)
        float sacc[4][4] = {};
        #pragma unroll 2
        for (int c0 = 0; c0 < 32; c0++) {
            int cc = ((c0 + tx) & 31) * 4;
            float4 qv[4], kv[4];
            #pragma unroll
            for (int m = 0; m < 4; m++) qv[m] = *(const float4*)(Qs + (ty*4+m)*HDP + cc);
            #pragma unroll
            for (int n = 0; n < 4; n++) kv[n] = *(const float4*)(Ks + (tx*4+n)*HDP + cc);
            #pragma unroll
            for (int m = 0; m < 4; m++)
                #pragma unroll
                for (int n = 0; n < 4; n++) {
                    sacc[m][n] = fmaf(qv[m].x, kv[n].x, sacc[m][n]);
                    sacc[m][n] = fmaf(qv[m].y, kv[n].y, sacc[m][n]);
                    sacc[m][n] = fmaf(qv[m].z, kv[n].z, sacc[m][n]);
                    sacc[m][n] = fmaf(qv[m].w, kv[n].w, sacc[m][n]);
                }
        }
        bool diag = (kt == qt);
        #pragma unroll
        for (int m = 0; m < 4; m++) {
            int r = ty*4 + m;
            #pragma unroll
            for (int n = 0; n < 4; n++) {
                int c = tx*4 + n;
                float s = sacc[m][n] * scale;
                if (diag && c > r) s = -CUDART_INF_F;
                Ss[r*SSP + c] = s;
            }
        }
        __syncthreads();

        if (tid < ABQ) {
            int r = tid;
            float mold = rowM[r];
            float mx = mold;
            for (int j = 0; j < ABK; j++) mx = fmaxf(mx, Ss[r*SSP + j]);
            float corr = expf(mold - mx);
            float sum = 0.0f;
            for (int j = 0; j < ABK; j++) {
                float p = expf(Ss[r*SSP + j] - mx);
                Ss[r*SSP + j] = p;
                sum += p;
            }
            rowM[r] = mx;
            rowL[r] = rowL[r] * corr + sum;
            rowC[r] = corr;
        }
        __syncthreads();

        float cr[4];
        #pragma unroll
        for (int m = 0; m < 4; m++) cr[m] = rowC[ty*4+m];
        #pragma unroll
        for (int m = 0; m < 4; m++)
            #pragma unroll
            for (int n = 0; n < 8; n++) acc[m][n] *= cr[m];

        for (int j = 0; j < ABK; j++) {
            float rp[4];
            #pragma unroll
            for (int m = 0; m < 4; m++) rp[m] = Ss[(ty*4+m)*SSP + j];
            float4 v0 = *(const float4*)(Vs + j*HDP + tx*8);
            float4 v1 = *(const float4*)(Vs + j*HDP + tx*8 + 4);
            float rv[8] = {v0.x,v0.y,v0.z,v0.w,v1.x,v1.y,v1.z,v1.w};
            #pragma unroll
            for (int m = 0; m < 4; m++)
                #pragma unroll
                for (int n = 0; n < 8; n++)
                    acc[m][n] = fmaf(rp[m], rv[n], acc[m][n]);
        }
    }

    #pragma unroll
    for (int m = 0; m < 4; m++) {
        int r = ty*4 + m;
        float invl = 1.0f / rowL[r];
        float* dst = Y + ((size_t)(b*TSEQ + q0 + r)) * DIM + h*HD + tx*8;
        float4 o0 = make_float4(acc[m][0]*invl, acc[m][1]*invl, acc[m][2]*invl, acc[m][3]*invl);
        float4 o1 = make_float4(acc[m][4]*invl, acc[m][5]*invl, acc[m][6]*invl, acc[m][7]*invl);
        *(float4*)(dst)     = o0;
        *(float4*)(dst + 4) = o1;
    }
}

// ---------------- v-direction projection removal ---------------------------
__global__ void vproj_kernel(const float* __restrict__ V, int vstride,
                             float* __restrict__ Y)
{
    int gthr = blockIdx.x * blockDim.x + threadIdx.x;
    int w    = gthr >> 5;
    int lane = gthr & 31;
    if (w >= BT * NHKV) return;
    int bt = w / NHKV, kh = w % NHKV;

    const float* vrow = V + (size_t)bt * vstride + kh * HD;
    float v0 = vrow[lane], v1 = vrow[lane+32], v2 = vrow[lane+64], v3 = vrow[lane+96];
    float ss = v0*v0 + v1*v1 + v2*v2 + v3*v3;
    #pragma unroll
    for (int o = 16; o; o >>= 1) ss += __shfl_xor_sync(0xffffffffu, ss, o);
    float norm = sqrtf(ss);
    float inv = 1.0f / fmaxf(norm, 1e-12f);
    float n0 = v0*inv, n1 = v1*inv, n2 = v2*inv, n3 = v3*inv;

    #pragma unroll
    for (int g = 0; g < GROUP; g++) {
        int hh = kh * GROUP + g;
        float* yrow = Y + (size_t)bt * DIM + hh * HD;
        float y0 = yrow[lane], y1 = yrow[lane+32], y2 = yrow[lane+64], y3 = yrow[lane+96];
        float d = y0*n0 + y1*n1 + y2*n2 + y3*n3;
        #pragma unroll
        for (int o = 16; o; o >>= 1) d += __shfl_xor_sync(0xffffffffu, d, o);
        yrow[lane]    = y0 - d*n0;
        yrow[lane+32] = y1 - d*n1;
        yrow[lane+64] = y2 - d*n2;
        yrow[lane+96] = y3 - d*n3;
    }
}

// ---------------- launcher --------------------------------------------------
extern "C" void kernel_launch(void* const* d_in, const int* in_sizes, int n_in,
                              void* d_out, int out_size)
{
    const float* x     = (const float*)d_in[0];
    const float* Wq    = (const float*)d_in[1];
    const float* Wk    = (const float*)d_in[2];
    const float* Wv    = (const float*)d_in[3];
    const float* Wp    = (const float*)d_in[4];
    const float* qgain = (const float*)d_in[5];
    const float* qA    = (const float*)d_in[6];
    const float* qB    = (const float*)d_in[7];
    const float* kA    = (const float*)d_in[8];
    const float* kB    = (const float*)d_in[9];
    const float* vA    = (const float*)d_in[10];
    const float* vB    = (const float*)d_in[11];
    const float* pA    = (const float*)d_in[12];
    const float* pB    = (const float*)d_in[13];
    float* out = (float*)d_out;

    __nv_bfloat16 *wh, *wl, *wph, *wpl, *xh, *xl, *yh, *yl;
    float *qkv, *y;
    cudaGetSymbolAddress((void**)&wh,  g_WqkvTh); cudaGetSymbolAddress((void**)&wl,  g_WqkvTl);
    cudaGetSymbolAddress((void**)&wph, g_WpTh);   cudaGetSymbolAddress((void**)&wpl, g_WpTl);
    cudaGetSymbolAddress((void**)&xh,  g_xh);     cudaGetSymbolAddress((void**)&xl,  g_xl);
    cudaGetSymbolAddress((void**)&yh,  g_yh);     cudaGetSymbolAddress((void**)&yl,  g_yl);
    cudaGetSymbolAddress((void**)&qkv, g_qkv);
    cudaGetSymbolAddress((void**)&y,   g_y);

    const int GSMEM = (8*TBM*STR) * (int)sizeof(__nv_bfloat16);
    cudaFuncSetAttribute(bf16x3gemm_kernel, cudaFuncAttributeMaxDynamicSharedMemorySize, GSMEM);

    // 1) fold LoRA, transpose, split (coalesced). Pack Wq|Wk|Wv rows.
    dim3 tb(32, 8);
    effw_splitT_kernel<<<dim3(DIM/32,   DIM/32), tb>>>(Wq, qA, qB, wh,                 wl,                 DIM);
    effw_splitT_kernel<<<dim3(KVDIM/32, DIM/32), tb>>>(Wk, kA, kB, wh + (size_t)KOFF*DIM, wl + (size_t)KOFF*DIM, KVDIM);
    effw_splitT_kernel<<<dim3(KVDIM/32, DIM/32), tb>>>(Wv, vA, vB, wh + (size_t)VOFF*DIM, wl + (size_t)VOFF*DIM, KVDIM);
    effw_splitT_kernel<<<dim3(DIM/32,   DIM/32), tb>>>(Wp, pA, pB, wph,                wpl,                DIM);
    split_kernel<<<(BT*DIM/4 + 255)/256, 256>>>(x, BT*DIM/4, xh, xl);

    // 2) fused qkv projection (bf16x3 tensor cores), N = 3072
    dim3 gqkv(QKVD/TBN, BT/TBM);
    bf16x3gemm_kernel<<<gqkv, 128, GSMEM>>>(BT, QKVD, DIM, xh, xl, wh, wl, qkv);

    // 3) per-head RMSnorm + RoPE (+gain on q)
    {
        int wq_n = BT * NH;
        int wk_n = BT * NHKV;
        normrope_kernel<<<(wq_n*32 + 255)/256, 256>>>(qkv,        NH,   QKVD, qgain);
        normrope_kernel<<<(wk_n*32 + 255)/256, 256>>>(qkv + KOFF, NHKV, QKVD, nullptr);
    }

    // 4) causal attention (flash style, fp32, conflict-free)
    {
        const int ATT_SMEM = (3*ABQ*HDP + ABQ*SSP + 3*ABQ) * (int)sizeof(float);
        cudaFuncSetAttribute(attn_kernel, cudaFuncAttributeMaxDynamicSharedMemorySize, ATT_SMEM);
        dim3 ga(TSEQ/ABQ, NH, BSZ);
        attn_kernel<<<ga, 256, ATT_SMEM>>>(qkv, y);
    }

    // 5) remove projection onto normalized v
    {
        int wv_n = BT * NHKV;
        vproj_kernel<<<(wv_n*32 + 255)/256, 256>>>(qkv + VOFF, QKVD, y);
    }

    // 6) output projection (bf16x3 tensor cores)
    split_kernel<<<(BT*DIM/4 + 255)/256, 256>>>(y, BT*DIM/4, yh, yl);
    dim3 gp(DIM/TBN, BT/TBM);
    bf16x3gemm_kernel<<<gp, 128, GSMEM>>>(BT, DIM, DIM, yh, yl, wph, wpl, out);
}

// round 7
// speedup vs baseline: 3.5955x; 1.8800x over previous
#include <cuda_runtime.h>
#include <cuda_bf16.h>
#include <cuda_fp16.h>
#include <math.h>
#include <math_constants.h>
#include <stdint.h>

// Problem constants
#define BSZ   2
#define TSEQ  2048
#define DIM   2048
#define NH    16
#define NHKV  4
#define HD    128
#define KVDIM (NHKV*HD)     // 512
#define GROUP (NH/NHKV)     // 4
#define RANK  16
#define BT    (BSZ*TSEQ)    // 4096
#define QKVD  (DIM + 2*KVDIM)   // 3072
#define KOFF  DIM               // 2048
#define VOFF  (DIM + KVDIM)     // 2560

// ---------------- scratch (device globals; no allocation allowed) ----------
__device__ __nv_bfloat16 g_WqkvTh[QKVD*DIM], g_WqkvTl[QKVD*DIM];  // [3072][2048]
__device__ __nv_bfloat16 g_WpTh[DIM*DIM],    g_WpTl[DIM*DIM];
__device__ __nv_bfloat16 g_xh[BT*DIM],  g_xl[BT*DIM];
__device__ __nv_bfloat16 g_yh[BT*DIM],  g_yl[BT*DIM];
__device__ float g_qkv[BT*QKVD];
__device__ float g_y[BT*DIM];

// ---- effective weights W + A@B, transposed to [N][K], split bf16 hi/lo ----
__global__ void effw_splitT_kernel(const float* __restrict__ W,
                                   const float* __restrict__ A,
                                   const float* __restrict__ Bm,
                                   __nv_bfloat16* __restrict__ H,
                                   __nv_bfloat16* __restrict__ L, int N)
{
    __shared__ float tile[32][33];
    int tn = blockIdx.x * 32;
    int tk = blockIdx.y * 32;
    int tx = threadIdx.x, ty = threadIdx.y;   // 32 x 8

    #pragma unroll
    for (int i = 0; i < 4; i++) {
        int k = tk + ty + i*8;
        int n = tn + tx;
        float s = W[(size_t)k * N + n];
        #pragma unroll
        for (int r = 0; r < RANK; r++)
            s += A[k*RANK + r] * Bm[r*N + n];
        tile[ty + i*8][tx] = s;
    }
    __syncthreads();
    #pragma unroll
    for (int i = 0; i < 4; i++) {
        int n = tn + ty + i*8;
        int k = tk + tx;
        float s = tile[tx][ty + i*8];
        __nv_bfloat16 h = __float2bfloat16_rn(s);
        H[(size_t)n * DIM + k] = h;
        L[(size_t)n * DIM + k] = __float2bfloat16_rn(s - __bfloat162float(h));
    }
}

// ---- split fp32 activation into bf16 hi/lo (vectorized) --------------------
__global__ void split_kernel(const float* __restrict__ X, int count4,
                             __nv_bfloat16* __restrict__ H,
                             __nv_bfloat16* __restrict__ L)
{
    int idx = blockIdx.x * blockDim.x + threadIdx.x;
    if (idx >= count4) return;
    float4 v = ((const float4*)X)[idx];
    __nv_bfloat16 h0 = __float2bfloat16_rn(v.x), h1 = __float2bfloat16_rn(v.y);
    __nv_bfloat16 h2 = __float2bfloat16_rn(v.z), h3 = __float2bfloat16_rn(v.w);
    __nv_bfloat162 hh0 = {h0, h1}, hh1 = {h2, h3};
    __nv_bfloat162 ll0 = {__float2bfloat16_rn(v.x - __bfloat162float(h0)),
                          __float2bfloat16_rn(v.y - __bfloat162float(h1))};
    __nv_bfloat162 ll1 = {__float2bfloat16_rn(v.z - __bfloat162float(h2)),
                          __float2bfloat16_rn(v.w - __bfloat162float(h3))};
    ((__nv_bfloat162*)H)[idx*2]   = hh0;
    ((__nv_bfloat162*)H)[idx*2+1] = hh1;
    ((__nv_bfloat162*)L)[idx*2]   = ll0;
    ((__nv_bfloat162*)L)[idx*2+1] = ll1;
}

// ---------------- bf16x3 tensor-core GEMM (known-good, R4) ------------------
#define TBM 128
#define TBN 128
#define TBK 32
#define STR 40

__device__ __forceinline__ void cpa16(uint32_t dst, const void* src) {
    asm volatile("cp.async.ca.shared.global [%0], [%1], 16;\n" :: "r"(dst), "l"(src));
}
__device__ __forceinline__ void cpa_commit() {
    asm volatile("cp.async.commit_group;\n");
}
__device__ __forceinline__ void cpa_wait0() {
    asm volatile("cp.async.wait_group 0;\n");
}
__device__ __forceinline__ void mma_bf16(float& d0, float& d1, float& d2, float& d3,
                                         uint32_t a0, uint32_t a1, uint32_t a2, uint32_t a3,
                                         uint32_t b0, uint32_t b1) {
    asm volatile(
        "mma.sync.aligned.m16n8k16.row.col.f32.bf16.bf16.f32 "
        "{%0,%1,%2,%3}, {%4,%5,%6,%7}, {%8,%9}, {%0,%1,%2,%3};\n"
        : "+f"(d0), "+f"(d1), "+f"(d2), "+f"(d3)
        : "r"(a0), "r"(a1), "r"(a2), "r"(a3), "r"(b0), "r"(b1));
}
__device__ __forceinline__ void mma_f16(float& d0, float& d1, float& d2, float& d3,
                                        uint32_t a0, uint32_t a1, uint32_t a2, uint32_t a3,
                                        uint32_t b0, uint32_t b1) {
    asm volatile(
        "mma.sync.aligned.m16n8k16.row.col.f32.f16.f16.f32 "
        "{%0,%1,%2,%3}, {%4,%5,%6,%7}, {%8,%9}, {%0,%1,%2,%3};\n"
        : "+f"(d0), "+f"(d1), "+f"(d2), "+f"(d3)
        : "r"(a0), "r"(a1), "r"(a2), "r"(a3), "r"(b0), "r"(b1));
}

__global__ __launch_bounds__(128)
void bf16x3gemm_kernel(int M, int N, int K,
                       const __nv_bfloat16* __restrict__ Ah,
                       const __nv_bfloat16* __restrict__ Al,
                       const __nv_bfloat16* __restrict__ Bh,   // [N][K]
                       const __nv_bfloat16* __restrict__ Bl,
                       float* __restrict__ C)
{
    extern __shared__ __nv_bfloat16 smem[];
    __nv_bfloat16* sAh = smem;
    __nv_bfloat16* sAl = sAh + 2*TBM*STR;
    __nv_bfloat16* sBh = sAl + 2*TBM*STR;
    __nv_bfloat16* sBl = sBh + 2*TBN*STR;

    int tid  = threadIdx.x;
    int warp = tid >> 5, lane = tid & 31;
    int warpM = warp >> 1, warpN = warp & 1;
    int gid = lane >> 2, tig = lane & 3;

    const __nv_bfloat16* Ahb = Ah + (size_t)blockIdx.y * TBM * K;
    const __nv_bfloat16* Alb = Al + (size_t)blockIdx.y * TBM * K;
    const __nv_bfloat16* Bhb = Bh + (size_t)blockIdx.x * TBN * K;
    const __nv_bfloat16* Blb = Bl + (size_t)blockIdx.x * TBN * K;
    float* Cb = C + (size_t)blockIdx.y * TBM * N + (size_t)blockIdx.x * TBN;

    int srow = tid >> 2;
    int scol = (tid & 3) * 8;

    uint32_t uAh = (uint32_t)__cvta_generic_to_shared(sAh);
    uint32_t uAl = (uint32_t)__cvta_generic_to_shared(sAl);
    uint32_t uBh = (uint32_t)__cvta_generic_to_shared(sBh);
    uint32_t uBl = (uint32_t)__cvta_generic_to_shared(sBl);

    float acc[4][8][4];
    #pragma unroll
    for (int m = 0; m < 4; m++)
        #pragma unroll
        for (int n = 0; n < 8; n++)
            #pragma unroll
            for (int i = 0; i < 4; i++) acc[m][n][i] = 0.0f;

    int ntiles = K / TBK;

    auto issue = [&](int buf, int kt) {
        uint32_t bofs = (uint32_t)(buf * TBM * STR * 2);
        #pragma unroll
        for (int i = 0; i < 4; i++) {
            int r = srow + i * 32;
            uint32_t dofs = (uint32_t)((r * STR + scol) * 2);
            size_t gofs = (size_t)r * K + (size_t)kt * TBK + scol;
            cpa16(uAh + bofs + dofs, Ahb + gofs);
            cpa16(uAl + bofs + dofs, Alb + gofs);
            cpa16(uBh + bofs + dofs, Bhb + gofs);
            cpa16(uBl + bofs + dofs, Blb + gofs);
        }
        cpa_commit();
    };

    issue(0, 0);
    int buf = 0;

    for (int kt = 0; kt < ntiles; kt++) {
        cpa_wait0();
        __syncthreads();
        if (kt + 1 < ntiles) issue(buf ^ 1, kt + 1);

        const __nv_bfloat16* Ahs = sAh + buf * TBM * STR;
        const __nv_bfloat16* Als = sAl + buf * TBM * STR;
        const __nv_bfloat16* Bhs = sBh + buf * TBN * STR;
        const __nv_bfloat16* Bls = sBl + buf * TBN * STR;

        #pragma unroll
        for (int ks = 0; ks < TBK; ks += 16) {
            uint32_t afh[4][4], afl[4][4];
            #pragma unroll
            for (int mt = 0; mt < 4; mt++) {
                int r0 = warpM*64 + mt*16;
                const __nv_bfloat16* ah = Ahs + (size_t)r0 * STR + ks;
                const __nv_bfloat16* al = Als + (size_t)r0 * STR + ks;
                afh[mt][0] = *(const uint32_t*)(ah + (size_t) gid      * STR + 2*tig);
                afh[mt][1] = *(const uint32_t*)(ah + (size_t)(gid + 8) * STR + 2*tig);
                afh[mt][2] = *(const uint32_t*)(ah + (size_t) gid      * STR + 2*tig + 8);
                afh[mt][3] = *(const uint32_t*)(ah + (size_t)(gid + 8) * STR + 2*tig + 8);
                afl[mt][0] = *(const uint32_t*)(al + (size_t) gid      * STR + 2*tig);
                afl[mt][1] = *(const uint32_t*)(al + (size_t)(gid + 8) * STR + 2*tig);
                afl[mt][2] = *(const uint32_t*)(al + (size_t) gid      * STR + 2*tig + 8);
                afl[mt][3] = *(const uint32_t*)(al + (size_t)(gid + 8) * STR + 2*tig + 8);
            }
            uint32_t bfh[8][2], bfl[8][2];
            #pragma unroll
            for (int nt = 0; nt < 8; nt++) {
                int n0 = warpN*64 + nt*8 + gid;
                const __nv_bfloat16* bh = Bhs + (size_t)n0 * STR + ks;
                const __nv_bfloat16* bl = Bls + (size_t)n0 * STR + ks;
                bfh[nt][0] = *(const uint32_t*)(bh + 2*tig);
                bfh[nt][1] = *(const uint32_t*)(bh + 2*tig + 8);
                bfl[nt][0] = *(const uint32_t*)(bl + 2*tig);
                bfl[nt][1] = *(const uint32_t*)(bl + 2*tig + 8);
            }
            #pragma unroll
            for (int mt = 0; mt < 4; mt++)
                #pragma unroll
                for (int nt = 0; nt < 8; nt++) {
                    mma_bf16(acc[mt][nt][0], acc[mt][nt][1], acc[mt][nt][2], acc[mt][nt][3],
                             afh[mt][0], afh[mt][1], afh[mt][2], afh[mt][3],
                             bfh[nt][0], bfh[nt][1]);
                    mma_bf16(acc[mt][nt][0], acc[mt][nt][1], acc[mt][nt][2], acc[mt][nt][3],
                             afh[mt][0], afh[mt][1], afh[mt][2], afh[mt][3],
                             bfl[nt][0], bfl[nt][1]);
                    mma_bf16(acc[mt][nt][0], acc[mt][nt][1], acc[mt][nt][2], acc[mt][nt][3],
                             afl[mt][0], afl[mt][1], afl[mt][2], afl[mt][3],
                             bfh[nt][0], bfh[nt][1]);
                }
        }
        __syncthreads();
        buf ^= 1;
    }

    #pragma unroll
    for (int mt = 0; mt < 4; mt++) {
        int r0 = warpM*64 + mt*16 + gid;
        #pragma unroll
        for (int nt = 0; nt < 8; nt++) {
            int c0 = warpN*64 + nt*8 + tig*2;
            *(float2*)(Cb + (size_t) r0      * N + c0) = make_float2(acc[mt][nt][0], acc[mt][nt][1]);
            *(float2*)(Cb + (size_t)(r0 + 8) * N + c0) = make_float2(acc[mt][nt][2], acc[mt][nt][3]);
        }
    }
}

// ---------------- RMSnorm + RoPE (+gain) : one warp per (b,t,head) ---------
__global__ void normrope_kernel(float* __restrict__ X, int nheads, int rowdim,
                                const float* __restrict__ gain)
{
    int gthr = blockIdx.x * blockDim.x + threadIdx.x;
    int w    = gthr >> 5;
    int lane = gthr & 31;
    int total = BT * nheads;
    if (w >= total) return;
    int bt = w / nheads, hh = w % nheads;
    int t = bt % TSEQ;

    float* row = X + (size_t)bt * rowdim + hh * HD;
    float v0 = row[lane], v1 = row[lane+32], v2 = row[lane+64], v3 = row[lane+96];

    float ss = v0*v0 + v1*v1 + v2*v2 + v3*v3;
    #pragma unroll
    for (int o = 16; o; o >>= 1) ss += __shfl_xor_sync(0xffffffffu, ss, o);

    float f = rsqrtf(ss * (1.0f/128.0f) + 1.1920929e-7f);
    if (gain) f *= gain[hh];

    float invfreq = powf(10000.0f, -(float)lane * (1.0f/32.0f));
    float ang = (float)t * invfreq;
    float s, c;
    sincosf(ang, &s, &c);

    row[lane]    = ( v0*c + v1*s) * f;
    row[lane+32] = (-v0*s + v1*c) * f;
    row[lane+64] = v2 * f;
    row[lane+96] = v3 * f;
}

// ---------------- fp16 tensor-core causal flash attention ------------------
// 128 q rows per CTA, 8 warps x 16 rows, K/V tiles of 64.
// S and softmax in fp32; Q/K/V/P inputs in fp16. P repacked in registers.
// Strides: Q/K rows are 128 halves -> stride 136 (pad 8); Vt rows are 64 -> 72.
#define AQ   128
#define AK   64
#define QSTR 136
#define KSTR 136
#define VSTR 72
#define ATT_SMEM_H ((AQ*QSTR + AK*KSTR + HD*VSTR) * 2)   // 70656 bytes

__global__ __launch_bounds__(256)
void attn_mma_kernel(const float* __restrict__ QKV, float* __restrict__ Y)
{
    extern __shared__ __half smh[];
    __half* Qs = smh;                 // [AQ][QSTR]
    __half* Ks = Qs + AQ*QSTR;        // [AK][KSTR]
    __half* Vt = Ks + AK*KSTR;        // [HD][VSTR] (transposed V)

    int qt = blockIdx.x, h = blockIdx.y, b = blockIdx.z;
    int kh = h / GROUP;
    int q0 = qt * AQ;
    int tid = threadIdx.x;
    int warp = tid >> 5, lane = tid & 31;
    int gid = lane >> 2, tig = lane & 3;
    int wr = warp * 16;

    const float scale = 0.08838834764831845f;  // 128^-0.5

    // load Q tile fp32 -> fp16 smem
    for (int e = tid; e < AQ*32; e += 256) {
        int r = e >> 5, c4 = (e & 31) * 4;
        float4 v = *(const float4*)(QKV + (size_t)(b*TSEQ + q0 + r)*QKVD + h*HD + c4);
        __half* d = Qs + r*QSTR + c4;
        *(__half2*)(d)     = __floats2half2_rn(v.x, v.y);
        *(__half2*)(d + 2) = __floats2half2_rn(v.z, v.w);
    }

    float m0 = -CUDART_INF_F, m1 = -CUDART_INF_F;
    float l0 = 0.0f, l1 = 0.0f;
    float o[16][4];
    #pragma unroll
    for (int on = 0; on < 16; on++)
        #pragma unroll
        for (int i = 0; i < 4; i++) o[on][i] = 0.0f;

    int nkt = 2*qt + 2;
    for (int kt = 0; kt < nkt; kt++) {
        int s0 = kt * AK;
        __syncthreads();
        // K tile: [64][128] fp16
        for (int e = tid; e < AK*32; e += 256) {
            int r = e >> 5, c4 = (e & 31) * 4;
            float4 v = *(const float4*)(QKV + KOFF + (size_t)(b*TSEQ + s0 + r)*QKVD + kh*HD + c4);
            __half* d = Ks + r*KSTR + c4;
            *(__half2*)(d)     = __floats2half2_rn(v.x, v.y);
            *(__half2*)(d + 2) = __floats2half2_rn(v.z, v.w);
        }
        // V tile transposed: Vt[hd][s], written as half2 {V[s],V[s+1]}
        {
            int p  = tid & 31;    // s pair: rows 2p, 2p+1
            int cq = tid >> 5;    // col chunk: cols cq*16 .. cq*16+15
            const float* v0p = QKV + VOFF + (size_t)(b*TSEQ + s0 + 2*p)*QKVD + kh*HD + cq*16;
            const float* v1p = v0p + QKVD;
            #pragma unroll
            for (int j = 0; j < 4; j++) {
                float4 a = *(const float4*)(v0p + j*4);
                float4 bb = *(const float4*)(v1p + j*4);
                int cb = cq*16 + j*4;
                *(__half2*)(Vt + (cb+0)*VSTR + 2*p) = __floats2half2_rn(a.x, bb.x);
                *(__half2*)(Vt + (cb+1)*VSTR + 2*p) = __floats2half2_rn(a.y, bb.y);
                *(__half2*)(Vt + (cb+2)*VSTR + 2*p) = __floats2half2_rn(a.z, bb.z);
                *(__half2*)(Vt + (cb+3)*VSTR + 2*p) = __floats2half2_rn(a.w, bb.w);
            }
        }
        __syncthreads();

        // S = Q K^T  (warp rows wr..wr+15, cols 0..63): 8 ntiles x 4 fp32
        float sacc[8][4];
        #pragma unroll
        for (int nt = 0; nt < 8; nt++)
            #pragma unroll
            for (int i = 0; i < 4; i++) sacc[nt][i] = 0.0f;

        #pragma unroll
        for (int ks = 0; ks < 8; ks++) {
            const __half* qb = Qs + (wr + gid)*QSTR + ks*16 + 2*tig;
            uint32_t a0 = *(const uint32_t*)(qb);
            uint32_t a1 = *(const uint32_t*)(qb + 8*QSTR);
            uint32_t a2 = *(const uint32_t*)(qb + 8);
            uint32_t a3 = *(const uint32_t*)(qb + 8*QSTR + 8);
            #pragma unroll
            for (int nt = 0; nt < 8; nt++) {
                const __half* kb = Ks + (nt*8 + gid)*KSTR + ks*16 + 2*tig;
                uint32_t b0 = *(const uint32_t*)(kb);
                uint32_t b1 = *(const uint32_t*)(kb + 8);
                mma_f16(sacc[nt][0], sacc[nt][1], sacc[nt][2], sacc[nt][3],
                        a0, a1, a2, a3, b0, b1);
            }
        }

        // scale + causal mask
        #pragma unroll
        for (int nt = 0; nt < 8; nt++)
            #pragma unroll
            for (int i = 0; i < 4; i++) sacc[nt][i] *= scale;

        if (s0 + AK - 1 > q0 + wr) {
            int r0g = q0 + wr + gid;
            #pragma unroll
            for (int nt = 0; nt < 8; nt++) {
                int sb = s0 + nt*8 + 2*tig;
                if (sb     > r0g)     sacc[nt][0] = -CUDART_INF_F;
                if (sb + 1 > r0g)     sacc[nt][1] = -CUDART_INF_F;
                if (sb     > r0g + 8) sacc[nt][2] = -CUDART_INF_F;
                if (sb + 1 > r0g + 8) sacc[nt][3] = -CUDART_INF_F;
            }
        }

        // online softmax (rows gid -> m0/l0, gid+8 -> m1/l1)
        float mx0 = -CUDART_INF_F, mx1 = -CUDART_INF_F;
        #pragma unroll
        for (int nt = 0; nt < 8; nt++) {
            mx0 = fmaxf(mx0, fmaxf(sacc[nt][0], sacc[nt][1]));
            mx1 = fmaxf(mx1, fmaxf(sacc[nt][2], sacc[nt][3]));
        }
        #pragma unroll
        for (int off = 1; off <= 2; off <<= 1) {
            mx0 = fmaxf(mx0, __shfl_xor_sync(0xffffffffu, mx0, off));
            mx1 = fmaxf(mx1, __shfl_xor_sync(0xffffffffu, mx1, off));
        }
        float mn0 = fmaxf(m0, mx0), mn1 = fmaxf(m1, mx1);
        float corr0 = __expf(m0 - mn0), corr1 = __expf(m1 - mn1);
        m0 = mn0; m1 = mn1;

        float sum0 = 0.0f, sum1 = 0.0f;
        #pragma unroll
        for (int nt = 0; nt < 8; nt++) {
            sacc[nt][0] = __expf(sacc[nt][0] - mn0);
            sacc[nt][1] = __expf(sacc[nt][1] - mn0);
            sacc[nt][2] = __expf(sacc[nt][2] - mn1);
            sacc[nt][3] = __expf(sacc[nt][3] - mn1);
            sum0 += sacc[nt][0] + sacc[nt][1];
            sum1 += sacc[nt][2] + sacc[nt][3];
        }
        #pragma unroll
        for (int off = 1; off <= 2; off <<= 1) {
            sum0 += __shfl_xor_sync(0xffffffffu, sum0, off);
            sum1 += __shfl_xor_sync(0xffffffffu, sum1, off);
        }
        l0 = l0 * corr0 + sum0;
        l1 = l1 * corr1 + sum1;

        // rescale O
        #pragma unroll
        for (int on = 0; on < 16; on++) {
            o[on][0] *= corr0; o[on][1] *= corr0;
            o[on][2] *= corr1; o[on][3] *= corr1;
        }

        // O += P V : P repacked from S fragments in registers
        #pragma unroll
        for (int ks2 = 0; ks2 < 4; ks2++) {
            __half2 pa0 = __floats2half2_rn(sacc[2*ks2][0],   sacc[2*ks2][1]);
            __half2 pa1 = __floats2half2_rn(sacc[2*ks2][2],   sacc[2*ks2][3]);
            __half2 pa2 = __floats2half2_rn(sacc[2*ks2+1][0], sacc[2*ks2+1][1]);
            __half2 pa3 = __floats2half2_rn(sacc[2*ks2+1][2], sacc[2*ks2+1][3]);
            uint32_t a0 = *reinterpret_cast<uint32_t*>(&pa0);
            uint32_t a1 = *reinterpret_cast<uint32_t*>(&pa1);
            uint32_t a2 = *reinterpret_cast<uint32_t*>(&pa2);
            uint32_t a3 = *reinterpret_cast<uint32_t*>(&pa3);
            #pragma unroll
            for (int on = 0; on < 16; on++) {
                const __half* vb = Vt + (on*8 + gid)*VSTR + ks2*16 + 2*tig;
                uint32_t b0 = *(const uint32_t*)(vb);
                uint32_t b1 = *(const uint32_t*)(vb + 8);
                mma_f16(o[on][0], o[on][1], o[on][2], o[on][3],
                        a0, a1, a2, a3, b0, b1);
            }
        }
    }

    // write out
    float il0 = 1.0f / l0, il1 = 1.0f / l1;
    int r0 = q0 + wr + gid;
    #pragma unroll
    for (int on = 0; on < 16; on++) {
        int c0 = h*HD + on*8 + 2*tig;
        *(float2*)(Y + (size_t)(b*TSEQ + r0)     * DIM + c0) = make_float2(o[on][0]*il0, o[on][1]*il0);
        *(float2*)(Y + (size_t)(b*TSEQ + r0 + 8) * DIM + c0) = make_float2(o[on][2]*il1, o[on][3]*il1);
    }
}

// ---------------- v-direction projection removal ---------------------------
__global__ void vproj_kernel(const float* __restrict__ V, int vstride,
                             float* __restrict__ Y)
{
    int gthr = blockIdx.x * blockDim.x + threadIdx.x;
    int w    = gthr >> 5;
    int lane = gthr & 31;
    if (w >= BT * NHKV) return;
    int bt = w / NHKV, kh = w % NHKV;

    const float* vrow = V + (size_t)bt * vstride + kh * HD;
    float v0 = vrow[lane], v1 = vrow[lane+32], v2 = vrow[lane+64], v3 = vrow[lane+96];
    float ss = v0*v0 + v1*v1 + v2*v2 + v3*v3;
    #pragma unroll
    for (int o = 16; o; o >>= 1) ss += __shfl_xor_sync(0xffffffffu, ss, o);
    float norm = sqrtf(ss);
    float inv = 1.0f / fmaxf(norm, 1e-12f);
    float n0 = v0*inv, n1 = v1*inv, n2 = v2*inv, n3 = v3*inv;

    #pragma unroll
    for (int g = 0; g < GROUP; g++) {
        int hh = kh * GROUP + g;
        float* yrow = Y + (size_t)bt * DIM + hh * HD;
        float y0 = yrow[lane], y1 = yrow[lane+32], y2 = yrow[lane+64], y3 = yrow[lane+96];
        float d = y0*n0 + y1*n1 + y2*n2 + y3*n3;
        #pragma unroll
        for (int o = 16; o; o >>= 1) d += __shfl_xor_sync(0xffffffffu, d, o);
        yrow[lane]    = y0 - d*n0;
        yrow[lane+32] = y1 - d*n1;
        yrow[lane+64] = y2 - d*n2;
        yrow[lane+96] = y3 - d*n3;
    }
}

// ---------------- launcher --------------------------------------------------
extern "C" void kernel_launch(void* const* d_in, const int* in_sizes, int n_in,
                              void* d_out, int out_size)
{
    const float* x     = (const float*)d_in[0];
    const float* Wq    = (const float*)d_in[1];
    const float* Wk    = (const float*)d_in[2];
    const float* Wv    = (const float*)d_in[3];
    const float* Wp    = (const float*)d_in[4];
    const float* qgain = (const float*)d_in[5];
    const float* qA    = (const float*)d_in[6];
    const float* qB    = (const float*)d_in[7];
    const float* kA    = (const float*)d_in[8];
    const float* kB    = (const float*)d_in[9];
    const float* vA    = (const float*)d_in[10];
    const float* vB    = (const float*)d_in[11];
    const float* pA    = (const float*)d_in[12];
    const float* pB    = (const float*)d_in[13];
    float* out = (float*)d_out;

    __nv_bfloat16 *wh, *wl, *wph, *wpl, *xh, *xl, *yh, *yl;
    float *qkv, *y;
    cudaGetSymbolAddress((void**)&wh,  g_WqkvTh); cudaGetSymbolAddress((void**)&wl,  g_WqkvTl);
    cudaGetSymbolAddress((void**)&wph, g_WpTh);   cudaGetSymbolAddress((void**)&wpl, g_WpTl);
    cudaGetSymbolAddress((void**)&xh,  g_xh);     cudaGetSymbolAddress((void**)&xl,  g_xl);
    cudaGetSymbolAddress((void**)&yh,  g_yh);     cudaGetSymbolAddress((void**)&yl,  g_yl);
    cudaGetSymbolAddress((void**)&qkv, g_qkv);
    cudaGetSymbolAddress((void**)&y,   g_y);

    const int GSMEM = (8*TBM*STR) * (int)sizeof(__nv_bfloat16);
    cudaFuncSetAttribute(bf16x3gemm_kernel, cudaFuncAttributeMaxDynamicSharedMemorySize, GSMEM);

    // 1) fold LoRA, transpose, split (coalesced). Pack Wq|Wk|Wv rows.
    dim3 tb(32, 8);
    effw_splitT_kernel<<<dim3(DIM/32,   DIM/32), tb>>>(Wq, qA, qB, wh,                 wl,                 DIM);
    effw_splitT_kernel<<<dim3(KVDIM/32, DIM/32), tb>>>(Wk, kA, kB, wh + (size_t)KOFF*DIM, wl + (size_t)KOFF*DIM, KVDIM);
    effw_splitT_kernel<<<dim3(KVDIM/32, DIM/32), tb>>>(Wv, vA, vB, wh + (size_t)VOFF*DIM, wl + (size_t)VOFF*DIM, KVDIM);
    effw_splitT_kernel<<<dim3(DIM/32,   DIM/32), tb>>>(Wp, pA, pB, wph,                wpl,                DIM);
    split_kernel<<<(BT*DIM/4 + 255)/256, 256>>>(x, BT*DIM/4, xh, xl);

    // 2) fused qkv projection (bf16x3), N = 3072
    dim3 gqkv(QKVD/TBN, BT/TBM);
    bf16x3gemm_kernel<<<gqkv, 128, GSMEM>>>(BT, QKVD, DIM, xh, xl, wh, wl, qkv);

    // 3) per-head RMSnorm + RoPE (+gain on q)
    {
        int wq_n = BT * NH;
        int wk_n = BT * NHKV;
        normrope_kernel<<<(wq_n*32 + 255)/256, 256>>>(qkv,        NH,   QKVD, qgain);
        normrope_kernel<<<(wk_n*32 + 255)/256, 256>>>(qkv + KOFF, NHKV, QKVD, nullptr);
    }

    // 4) causal flash attention (fp16 tensor cores, fp32 softmax)
    {
        cudaFuncSetAttribute(attn_mma_kernel, cudaFuncAttributeMaxDynamicSharedMemorySize, ATT_SMEM_H);
        dim3 ga(TSEQ/AQ, NH, BSZ);
        attn_mma_kernel<<<ga, 256, ATT_SMEM_H>>>(qkv, y);
    }

    // 5) remove projection onto normalized v
    {
        int wv_n = BT * NHKV;
        vproj_kernel<<<(wv_n*32 + 255)/256, 256>>>(qkv + VOFF, QKVD, y);
    }

    // 6) output projection (bf16x3)
    split_kernel<<<(BT*DIM/4 + 255)/256, 256>>>(y, BT*DIM/4, yh, yl);
    dim3 gp(DIM/TBN, BT/TBM);
    bf16x3gemm_kernel<<<gp, 128, GSMEM>>>(BT, DIM, DIM, yh, yl, wph, wpl, out);
}